// round 15
// baseline (speedup 1.0000x reference)
#include <cuda_runtime.h>
#include <cuda_bf16.h>
#include <math.h>
#include <stdint.h>

#define B_   4
#define CIN  256
#define CQ   32
#define N3   13824   // 24^3
#define M3   1728    // 12^3
#define KT   64      // keys per tile
#define NKT  (M3/KT) // 27
#define QT   128     // queries per CTA

// ---- warp MMA helpers (baseline PTX, sm_75/80+ features) ----
__device__ __forceinline__ uint32_t smem_to_u32(const void* p) {
    uint32_t a;
    asm("{ .reg .u64 t; cvta.to.shared.u64 t, %1; cvt.u32.u64 %0, t; }" : "=r"(a) : "l"(p));
    return a;
}
__device__ __forceinline__ void ldsm4(uint32_t* r, uint32_t a) {
    asm volatile("ldmatrix.sync.aligned.m8n8.x4.shared.b16 {%0,%1,%2,%3}, [%4];"
        : "=r"(r[0]), "=r"(r[1]), "=r"(r[2]), "=r"(r[3]) : "r"(a));
}
__device__ __forceinline__ void ldsm4t(uint32_t* r, uint32_t a) {
    asm volatile("ldmatrix.sync.aligned.m8n8.x4.trans.shared.b16 {%0,%1,%2,%3}, [%4];"
        : "=r"(r[0]), "=r"(r[1]), "=r"(r[2]), "=r"(r[3]) : "r"(a));
}
__device__ __forceinline__ void mmabf(float* c, const uint32_t* a, const uint32_t* b) {
    asm volatile("mma.sync.aligned.m16n8k16.row.col.f32.bf16.bf16.f32 "
        "{%0,%1,%2,%3}, {%4,%5,%6,%7}, {%8,%9}, {%0,%1,%2,%3};"
        : "+f"(c[0]), "+f"(c[1]), "+f"(c[2]), "+f"(c[3])
        : "r"(a[0]), "r"(a[1]), "r"(a[2]), "r"(a[3]), "r"(b[0]), "r"(b[1]));
}
__device__ __forceinline__ float ex2f(float x) {
    float r; asm("ex2.approx.ftz.f32 %0, %1;" : "=f"(r) : "f"(x)); return r;
}
// split (a,b) -> bf16x2 hi reg + bf16x2 lo reg
__device__ __forceinline__ void splitpair(float a, float b, uint32_t& hi, uint32_t& lo) {
    __nv_bfloat162 h = __floats2bfloat162_rn(a, b);
    float ra = a - __bfloat162float(h.x);
    float rb = b - __bfloat162float(h.y);
    __nv_bfloat162 l = __floats2bfloat162_rn(ra, rb);
    hi = *(uint32_t*)&h;
    lo = *(uint32_t*)&l;
}

// Scratch (device globals). Layouts:
//   g_f, g_graw, g_hraw : [b][c][n]  (channel-major)
//   g_gp                : [b][m][c]
//   g_hpT               : [b][c][m]
__device__ float g_f[B_ * CQ * N3];
__device__ float g_graw[B_ * CQ * N3];
__device__ float g_hraw[B_ * CQ * N3];
__device__ float g_gp[B_ * M3 * CQ];
__device__ float g_hpT[B_ * CQ * M3];

// ---------------------------------------------------------------------------
// Projection via mma.sync with register double-buffering of x/W chunks.
// out[96, n] = W[96,256] x x[256, n] (3-term split). Output [b][c][n].
// ---------------------------------------------------------------------------
#define PXSTR 272   // bytes per x row (128 bf16 + 8 pad)
#define PWSTR 80    // bytes per W row (32 bf16 + 8 pad)
#define PXHI 0
#define PXLO 8704
#define PWHI 17408
#define PWLO 25088
#define PSMEM 32768

__global__ __launch_bounds__(128) void proj_mma_kernel(
    const float* __restrict__ x,
    const float* __restrict__ Wf,
    const float* __restrict__ Wg,
    const float* __restrict__ Wh)
{
    __shared__ __align__(16) char sm[PSMEM];
    const uint32_t smb = smem_to_u32(sm);
    const int tid  = threadIdx.x;
    const int w    = tid >> 5;
    const int lane = tid & 31;
    const int b    = blockIdx.y;
    const int n0   = blockIdx.x * 128;

    const int a_r = lane & 15;
    const int a_c = (lane >> 4) << 3;
    // trans-pair lane components (x4.trans covering two adjacent n8 tiles)
    const int t4_r = (lane & 7) + 8 * ((lane >> 3) & 1);
    const int t4_c = 8 * ((lane >> 4) & 1);

    // thread's staging coordinates
    const int xrow = tid >> 2, xseg = tid & 3;        // x: 2 rows per thread pass
    const int wrow0 = tid >> 1, wseg = tid & 1;       // W: rows via 2 passes

    float4 xpre[8];
    float4 wpre[6];

    // prefetch chunk 0
    {
#pragma unroll
        for (int i = 0; i < 8; i++) {
            int idx = tid + i * 128;
            int row = idx >> 5, seg = idx & 31;
            xpre[i] = *(const float4*)(x + ((size_t)(b * CIN + row)) * N3 + n0 + 4 * seg);
        }
#pragma unroll
        for (int i = 0; i < 6; i++) {
            int idx = tid + i * 128;
            int row = idx >> 3, seg = idx & 7;
            const float* Wsrc = (row < 32) ? Wf : ((row < 64) ? Wg : Wh);
            wpre[i] = *(const float4*)(Wsrc + (row & 31) * CIN + 4 * seg);
        }
    }

    float oacc[96];
#pragma unroll
    for (int i = 0; i < 96; i++) oacc[i] = 0.f;

    for (int cc0 = 0; cc0 < CIN; cc0 += 32) {
        __syncthreads();
        // split-store prefetched chunk
#pragma unroll
        for (int i = 0; i < 8; i++) {
            int idx = tid + i * 128;
            int row = idx >> 5, seg = idx & 31;
            uint32_t h0, l0, h1, l1;
            splitpair(xpre[i].x, xpre[i].y, h0, l0);
            splitpair(xpre[i].z, xpre[i].w, h1, l1);
            *(uint2*)(sm + PXHI + row * PXSTR + 8 * seg) = make_uint2(h0, h1);
            *(uint2*)(sm + PXLO + row * PXSTR + 8 * seg) = make_uint2(l0, l1);
        }
#pragma unroll
        for (int i = 0; i < 6; i++) {
            int idx = tid + i * 128;
            int row = idx >> 3, seg = idx & 7;
            uint32_t h0, l0, h1, l1;
            splitpair(wpre[i].x, wpre[i].y, h0, l0);
            splitpair(wpre[i].z, wpre[i].w, h1, l1);
            *(uint2*)(sm + PWHI + row * PWSTR + 8 * seg) = make_uint2(h0, h1);
            *(uint2*)(sm + PWLO + row * PWSTR + 8 * seg) = make_uint2(l0, l1);
        }
        __syncthreads();

        // prefetch next chunk (overlaps with compute below)
        if (cc0 + 32 < CIN) {
#pragma unroll
            for (int i = 0; i < 8; i++) {
                int idx = tid + i * 128;
                int row = idx >> 5, seg = idx & 31;
                xpre[i] = *(const float4*)(x + ((size_t)(b * CIN + cc0 + 32 + row)) * N3 + n0 + 4 * seg);
            }
#pragma unroll
            for (int i = 0; i < 6; i++) {
                int idx = tid + i * 128;
                int row = idx >> 3, seg = idx & 7;
                const float* Wsrc = (row < 32) ? Wf : ((row < 64) ? Wg : Wh);
                wpre[i] = *(const float4*)(Wsrc + (row & 31) * CIN + cc0 + 32 + 4 * seg);
            }
        }

#pragma unroll
        for (int ks = 0; ks < 2; ks++) {
            // B frags via paired ldsm4.trans: ntp covers n-tiles (2ntp, 2ntp+1)
            uint32_t bh[2][4], bl[2][4];
#pragma unroll
            for (int ntp = 0; ntp < 2; ntp++) {
                uint32_t addr = smb + PXHI + (16 * ks + t4_r) * PXSTR + (32 * w + 16 * ntp + t4_c) * 2;
                ldsm4t(bh[ntp], addr);
                ldsm4t(bl[ntp], addr + (PXLO - PXHI));
            }
#pragma unroll
            for (int mt = 0; mt < 6; mt++) {
                uint32_t ah[4], al[4];
                uint32_t wadr = smb + PWHI + (16 * mt + a_r) * PWSTR + (16 * ks + a_c) * 2;
                ldsm4(ah, wadr);
                ldsm4(al, wadr + (PWLO - PWHI));
#pragma unroll
                for (int ntp = 0; ntp < 2; ntp++) {
#pragma unroll
                    for (int half = 0; half < 2; half++) {
                        float* c = &oacc[(mt * 4 + 2 * ntp + half) * 4];
                        mmabf(c, ah, &bh[ntp][2 * half]);
                        mmabf(c, al, &bh[ntp][2 * half]);
                        mmabf(c, ah, &bl[ntp][2 * half]);
                    }
                }
            }
        }
    }

    // store: C[m=outch][n=pos]
    const int gid = lane >> 2;
    const int qid = lane & 3;
#pragma unroll
    for (int mt = 0; mt < 6; mt++) {
        float* dst = (mt < 2) ? g_f : ((mt < 4) ? g_graw : g_hraw);
        int ch = ((16 * mt) & 31) + gid;
#pragma unroll
        for (int nt = 0; nt < 4; nt++) {
            const float* c = &oacc[(mt * 4 + nt) * 4];
            int pos = n0 + 32 * w + 8 * nt + 2 * qid;
            size_t r0 = ((size_t)(b * CQ + ch)) * N3 + pos;
            size_t r1 = ((size_t)(b * CQ + ch + 8)) * N3 + pos;
            *(float2*)(dst + r0) = make_float2(c[0], c[1]);
            *(float2*)(dst + r1) = make_float2(c[2], c[3]);
        }
    }
}

// ---------------------------------------------------------------------------
// 2x2x2 max pool: [b][c][n] -> g_gp [b][m][c], g_hpT [b][c][m]
// ---------------------------------------------------------------------------
__global__ void pool_kernel()
{
    int idx = blockIdx.x * 256 + threadIdx.x;
    const int total = B_ * CQ * M3;
    if (idx >= total) return;
    int m = idx % M3;
    int c = (idx / M3) % CQ;
    int b = idx / (M3 * CQ);
    int md = m / 144, mh = (m / 12) % 12, mw = m % 12;

    const float* gbase = g_graw + ((size_t)(b * CQ + c)) * N3;
    const float* hbase = g_hraw + ((size_t)(b * CQ + c)) * N3;
    int n00 = (2 * md) * 576 + (2 * mh) * 24 + 2 * mw;

    float gmax = -INFINITY, hmax = -INFINITY;
#pragma unroll
    for (int dd = 0; dd < 2; dd++)
#pragma unroll
        for (int dh = 0; dh < 2; dh++) {
            int n = n00 + dd * 576 + dh * 24;
            float2 gv = *(const float2*)(gbase + n);
            float2 hv = *(const float2*)(hbase + n);
            gmax = fmaxf(gmax, fmaxf(gv.x, gv.y));
            hmax = fmaxf(hmax, fmaxf(hv.x, hv.y));
        }
    g_gp[((size_t)(b * M3 + m)) * CQ + c] = gmax;
    g_hpT[((size_t)(b * CQ + c)) * N3 * 0 + ((size_t)(b * CQ + c)) * M3 + m] = hmax;
}

// ---------------------------------------------------------------------------
// Fused attention: register-resident P/O fragments + register double-buffered
// G/H staging + paired ldsm4 B-fragments.
// ---------------------------------------------------------------------------
#define FSTR 40
#define GSTR 40
#define HSTR 72
#define WSTR 40
#define FHI 0
#define FLO 10240
#define GHI 20480
#define GLO 25600
#define HHI 30720
#define HLO 35328
#define WVH 0
#define WVL 20480
#define ASMEM 40960

__global__ __launch_bounds__(128) void attn_mma_kernel(
    const float* __restrict__ x,
    const float* __restrict__ Wv,
    const float* __restrict__ gamma_p,
    float* __restrict__ out)
{
    __shared__ __align__(16) char sm[ASMEM];
    const uint32_t smb = smem_to_u32(sm);
    const int tid  = threadIdx.x;
    const int w    = tid >> 5;
    const int lane = tid & 31;
    const int b = blockIdx.y;
    const int qbase = blockIdx.x * QT;

    const float gma = *gamma_p;
    const float LOG2E = 1.4426950408889634f;

    const int a_r = lane & 15;
    const int a_c = (lane >> 4) << 3;
    // paired (non-trans) B-frag lane components: covers two adjacent n8 tiles
    const int b4_r = (lane & 7) + 8 * ((lane >> 4) & 1);
    const int b4_c = ((lane >> 3) & 1) << 3;

    // staging coordinates
    const int grow = tid & 63, ghalf = tid >> 6;
    const int hc = tid & 31, hj0 = (tid >> 5) * 16;

    // ---- load F tile from [b][c][n], fold log2e ----
    {
        const float* fb = g_f + (size_t)b * CQ * N3 + qbase + tid;
#pragma unroll
        for (int cp = 0; cp < 16; cp++) {
            float fa = fb[(size_t)(2 * cp) * N3] * LOG2E;
            float fc = fb[(size_t)(2 * cp + 1) * N3] * LOG2E;
            uint32_t h, l;
            splitpair(fa, fc, h, l);
            *(uint32_t*)(sm + FHI + (tid * FSTR + 2 * cp) * 2) = h;
            *(uint32_t*)(sm + FLO + (tid * FSTR + 2 * cp) * 2) = l;
        }
    }

    float4 gpre[4], hpre[4];
    {
        const float4* gsrc = (const float4*)(g_gp + ((size_t)(b * M3 + grow)) * CQ + 16 * ghalf);
        const float4* hsrc = (const float4*)(g_hpT + ((size_t)(b * CQ + hc)) * M3 + hj0);
#pragma unroll
        for (int i = 0; i < 4; i++) { gpre[i] = gsrc[i]; hpre[i] = hsrc[i]; }
    }

    float oacc[2][4][4];
#pragma unroll
    for (int rt = 0; rt < 2; rt++)
#pragma unroll
        for (int n = 0; n < 4; n++)
#pragma unroll
            for (int i = 0; i < 4; i++) oacc[rt][n][i] = 0.f;
    float lpart[4] = {0.f, 0.f, 0.f, 0.f};

    for (int kt = 0; kt < NKT; kt++) {
        __syncthreads();
        // split-store prefetched G (64 keys x 32 ch)
#pragma unroll
        for (int i = 0; i < 4; i++) {
            int c = 16 * ghalf + i * 4;
            uint32_t h0, l0, h1, l1;
            splitpair(gpre[i].x, gpre[i].y, h0, l0);
            splitpair(gpre[i].z, gpre[i].w, h1, l1);
            *(uint2*)(sm + GHI + (grow * GSTR + c) * 2) = make_uint2(h0, h1);
            *(uint2*)(sm + GLO + (grow * GSTR + c) * 2) = make_uint2(l0, l1);
        }
        // split-store prefetched H (32 ch x 64 keys)
#pragma unroll
        for (int i = 0; i < 4; i++) {
            int j = hj0 + i * 4;
            uint32_t h0, l0, h1, l1;
            splitpair(hpre[i].x, hpre[i].y, h0, l0);
            splitpair(hpre[i].z, hpre[i].w, h1, l1);
            *(uint2*)(sm + HHI + (hc * HSTR + j) * 2) = make_uint2(h0, h1);
            *(uint2*)(sm + HLO + (hc * HSTR + j) * 2) = make_uint2(l0, l1);
        }
        __syncthreads();

        // prefetch next tile (overlaps with compute)
        if (kt + 1 < NKT) {
            const int kb2 = (kt + 1) * KT;
            const float4* gsrc = (const float4*)(g_gp + ((size_t)(b * M3 + kb2 + grow)) * CQ + 16 * ghalf);
            const float4* hsrc = (const float4*)(g_hpT + ((size_t)(b * CQ + hc)) * M3 + kb2 + hj0);
#pragma unroll
            for (int i = 0; i < 4; i++) { gpre[i] = gsrc[i]; hpre[i] = hsrc[i]; }
        }

#pragma unroll
        for (int rt = 0; rt < 2; rt++) {
            // ---- S GEMM over 64 keys ----
            float sacc[8][4];
#pragma unroll
            for (int n = 0; n < 8; n++)
#pragma unroll
                for (int i = 0; i < 4; i++) sacc[n][i] = 0.f;

#pragma unroll
            for (int ks = 0; ks < 2; ks++) {
                uint32_t fh[4], fl[4];
                uint32_t fadr = smb + FHI + ((32 * w + 16 * rt + a_r) * FSTR + 16 * ks + a_c) * 2;
                ldsm4(fh, fadr);
                ldsm4(fl, fadr + FLO);
#pragma unroll
                for (int np = 0; np < 4; np++) {
                    uint32_t gh4[4], gl4[4];
                    uint32_t gadr = smb + GHI + ((16 * np + b4_r) * GSTR + 16 * ks + b4_c) * 2;
                    ldsm4(gh4, gadr);
                    ldsm4(gl4, gadr + (GLO - GHI));
#pragma unroll
                    for (int half = 0; half < 2; half++) {
                        float* c = sacc[2 * np + half];
                        mmabf(c, fh, &gh4[2 * half]);
                        mmabf(c, fl, &gh4[2 * half]);
                        mmabf(c, fh, &gl4[2 * half]);
                    }
                }
            }

            // ---- exp (base-2) + l partials ----
#pragma unroll
            for (int n = 0; n < 8; n++) {
#pragma unroll
                for (int i = 0; i < 4; i++) sacc[n][i] = ex2f(sacc[n][i]);
                lpart[rt * 2 + 0] += sacc[n][0] + sacc[n][1];
                lpart[rt * 2 + 1] += sacc[n][2] + sacc[n][3];
            }

            // ---- PV GEMM: P from registers ----
#pragma unroll
            for (int ks = 0; ks < 4; ks++) {
                uint32_t ph[4], pl[4];
                splitpair(sacc[2 * ks][0],     sacc[2 * ks][1],     ph[0], pl[0]);
                splitpair(sacc[2 * ks][2],     sacc[2 * ks][3],     ph[1], pl[1]);
                splitpair(sacc[2 * ks + 1][0], sacc[2 * ks + 1][1], ph[2], pl[2]);
                splitpair(sacc[2 * ks + 1][2], sacc[2 * ks + 1][3], ph[3], pl[3]);
#pragma unroll
                for (int np = 0; np < 2; np++) {
                    uint32_t hh4[4], hl4[4];
                    uint32_t hadr = smb + HHI + ((16 * np + b4_r) * HSTR + 16 * ks + b4_c) * 2;
                    ldsm4(hh4, hadr);
                    ldsm4(hl4, hadr + (HLO - HHI));
#pragma unroll
                    for (int half = 0; half < 2; half++) {
                        float* c = oacc[rt][2 * np + half];
                        mmabf(c, ph, &hh4[2 * half]);
                        mmabf(c, pl, &hh4[2 * half]);
                        mmabf(c, ph, &hl4[2 * half]);
                    }
                }
            }
        }
    }

    // ---- reduce l across quad lanes ----
    float inv[4];
#pragma unroll
    for (int i = 0; i < 4; i++) {
        float v = lpart[i];
        v += __shfl_xor_sync(0xFFFFFFFFu, v, 1);
        v += __shfl_xor_sync(0xFFFFFFFFu, v, 2);
        inv[i] = 1.0f / v;
    }

    // ---- build normalized O A-fragments in registers ----
    uint32_t ofh[2][2][4], ofl[2][2][4];
#pragma unroll
    for (int rt = 0; rt < 2; rt++) {
        float i0 = inv[rt * 2 + 0], i1 = inv[rt * 2 + 1];
#pragma unroll
        for (int ks = 0; ks < 2; ks++) {
            splitpair(oacc[rt][2 * ks][0] * i0,     oacc[rt][2 * ks][1] * i0,     ofh[rt][ks][0], ofl[rt][ks][0]);
            splitpair(oacc[rt][2 * ks][2] * i1,     oacc[rt][2 * ks][3] * i1,     ofh[rt][ks][1], ofl[rt][ks][1]);
            splitpair(oacc[rt][2 * ks + 1][0] * i0, oacc[rt][2 * ks + 1][1] * i0, ofh[rt][ks][2], ofl[rt][ks][2]);
            splitpair(oacc[rt][2 * ks + 1][2] * i1, oacc[rt][2 * ks + 1][3] * i1, ofh[rt][ks][3], ofl[rt][ks][3]);
        }
    }

    // ---- stage Wv (overlays F/G/H) ----
    __syncthreads();
#pragma unroll
    for (int h = 0; h < 2; h++) {
        int r = tid + 128 * h;
        const float4* src = (const float4*)(Wv + r * CQ);
#pragma unroll
        for (int i = 0; i < 8; i++) {
            float4 v = src[i];
            int c = i * 4;
            uint32_t h0, l0, h1, l1;
            splitpair(v.x, v.y, h0, l0);
            splitpair(v.z, v.w, h1, l1);
            *(uint2*)(sm + WVH + (r * WSTR + c) * 2) = make_uint2(h0, h1);
            *(uint2*)(sm + WVL + (r * WSTR + c) * 2) = make_uint2(l0, l1);
        }
    }
    __syncthreads();

    // ---- Out = O(128x32) . Wv(256x32)^T in 4 chunks of 64 couts ----
#pragma unroll 1
    for (int ch = 0; ch < 4; ch++) {
        float wacc[2][8][4];
#pragma unroll
        for (int rt = 0; rt < 2; rt++)
#pragma unroll
            for (int n = 0; n < 8; n++)
#pragma unroll
                for (int i = 0; i < 4; i++) wacc[rt][n][i] = 0.f;

#pragma unroll
        for (int ks = 0; ks < 2; ks++) {
#pragma unroll
            for (int np = 0; np < 4; np++) {
                uint32_t wh4[4], wl4[4];
                uint32_t wadr = smb + WVH + ((ch * 64 + 16 * np + b4_r) * WSTR + 16 * ks + b4_c) * 2;
                ldsm4(wh4, wadr);
                ldsm4(wl4, wadr + WVL);
#pragma unroll
                for (int half = 0; half < 2; half++) {
#pragma unroll
                    for (int rt = 0; rt < 2; rt++) {
                        float* c = wacc[rt][2 * np + half];
                        mmabf(c, ofh[rt][ks], &wh4[2 * half]);
                        mmabf(c, ofl[rt][ks], &wh4[2 * half]);
                        mmabf(c, ofh[rt][ks], &wl4[2 * half]);
                    }
                }
            }
        }

        // write out + residual (out layout [b][c][n])
#pragma unroll
        for (int rt = 0; rt < 2; rt++) {
            int q0 = qbase + 32 * w + 16 * rt + (lane >> 2);
#pragma unroll
            for (int n = 0; n < 8; n++) {
                int cc = ch * 64 + 8 * n + 2 * (lane & 3);
                size_t o0 = ((size_t)(b * CIN + cc)) * N3 + q0;
                out[o0]          = fmaf(gma, wacc[rt][n][0], x[o0]);
                out[o0 + N3]     = fmaf(gma, wacc[rt][n][1], x[o0 + N3]);
                out[o0 + 8]      = fmaf(gma, wacc[rt][n][2], x[o0 + 8]);
                out[o0 + N3 + 8] = fmaf(gma, wacc[rt][n][3], x[o0 + N3 + 8]);
            }
        }
    }
}

// ---------------------------------------------------------------------------
extern "C" void kernel_launch(void* const* d_in, const int* in_sizes, int n_in,
                              void* d_out, int out_size)
{
    const float* x     = (const float*)d_in[0];
    const float* Wf    = (const float*)d_in[1];
    const float* Wg    = (const float*)d_in[2];
    const float* Wh    = (const float*)d_in[3];
    const float* Wv    = (const float*)d_in[4];
    const float* gamma = (const float*)d_in[5];
    float* out = (float*)d_out;

    dim3 pgrid(N3 / 128, B_);
    proj_mma_kernel<<<pgrid, 128>>>(x, Wf, Wg, Wh);

    int ptotal = B_ * CQ * M3;
    pool_kernel<<<(ptotal + 255) / 256, 256>>>();

    dim3 agrid(N3 / QT, B_);
    attn_mma_kernel<<<agrid, 128>>>(x, Wv, gamma, out);
}

// round 16
// speedup vs baseline: 1.1990x; 1.1990x over previous
#include <cuda_runtime.h>
#include <cuda_bf16.h>
#include <math.h>
#include <stdint.h>

#define B_   4
#define CIN  256
#define CQ   32
#define N3   13824   // 24^3
#define M3   1728    // 12^3
#define KT   64      // keys per tile
#define NKT  (M3/KT) // 27
#define QT   128     // queries per CTA

// ---- warp MMA helpers (baseline PTX, sm_75/80+ features) ----
__device__ __forceinline__ uint32_t smem_to_u32(const void* p) {
    uint32_t a;
    asm("{ .reg .u64 t; cvta.to.shared.u64 t, %1; cvt.u32.u64 %0, t; }" : "=r"(a) : "l"(p));
    return a;
}
__device__ __forceinline__ void ldsm4(uint32_t* r, uint32_t a) {
    asm volatile("ldmatrix.sync.aligned.m8n8.x4.shared.b16 {%0,%1,%2,%3}, [%4];"
        : "=r"(r[0]), "=r"(r[1]), "=r"(r[2]), "=r"(r[3]) : "r"(a));
}
__device__ __forceinline__ void ldsm2(uint32_t* r, uint32_t a) {
    asm volatile("ldmatrix.sync.aligned.m8n8.x2.shared.b16 {%0,%1}, [%2];"
        : "=r"(r[0]), "=r"(r[1]) : "r"(a));
}
__device__ __forceinline__ void ldsm2t(uint32_t* r, uint32_t a) {
    asm volatile("ldmatrix.sync.aligned.m8n8.x2.trans.shared.b16 {%0,%1}, [%2];"
        : "=r"(r[0]), "=r"(r[1]) : "r"(a));
}
__device__ __forceinline__ void mmabf(float* c, const uint32_t* a, const uint32_t* b) {
    asm volatile("mma.sync.aligned.m16n8k16.row.col.f32.bf16.bf16.f32 "
        "{%0,%1,%2,%3}, {%4,%5,%6,%7}, {%8,%9}, {%0,%1,%2,%3};"
        : "+f"(c[0]), "+f"(c[1]), "+f"(c[2]), "+f"(c[3])
        : "r"(a[0]), "r"(a[1]), "r"(a[2]), "r"(a[3]), "r"(b[0]), "r"(b[1]));
}
__device__ __forceinline__ float ex2f(float x) {
    float r; asm("ex2.approx.ftz.f32 %0, %1;" : "=f"(r) : "f"(x)); return r;
}
__device__ __forceinline__ void cpasync16(uint32_t dst, const void* src) {
    asm volatile("cp.async.ca.shared.global [%0], [%1], 16;" :: "r"(dst), "l"(src));
}
#define CP_COMMIT() asm volatile("cp.async.commit_group;" ::: "memory")
#define CP_WAIT0()  asm volatile("cp.async.wait_group 0;" ::: "memory")

// split (a,b) -> bf16x2 hi reg + bf16x2 lo reg
__device__ __forceinline__ void splitpair(float a, float b, uint32_t& hi, uint32_t& lo) {
    __nv_bfloat162 h = __floats2bfloat162_rn(a, b);
    float ra = a - __bfloat162float(h.x);
    float rb = b - __bfloat162float(h.y);
    __nv_bfloat162 l = __floats2bfloat162_rn(ra, rb);
    hi = *(uint32_t*)&h;
    lo = *(uint32_t*)&l;
}

// Scratch (device globals). Layouts:
//   g_f, g_graw, g_hraw : [b][c][n]  (channel-major)
//   g_gp                : [b][m][c]
//   g_hpT               : [b][c][m]
__device__ float g_f[B_ * CQ * N3];
__device__ float g_graw[B_ * CQ * N3];
__device__ float g_hraw[B_ * CQ * N3];
__device__ float g_gp[B_ * M3 * CQ];
__device__ float g_hpT[B_ * CQ * M3];

// ---------------------------------------------------------------------------
// Projection via mma.sync + cp.async double-buffered staging.
// out[96, n] = W[96,256] x x[256, n] (3-term split). Output [b][c][n].
// ---------------------------------------------------------------------------
#define PXSTR 272   // bytes per x row (128 bf16 + 8 pad)
#define PWSTR 80    // bytes per W row (32 bf16 + 8 pad)
#define PXHI 0
#define PXLO 8704
#define PWHI 17408
#define PWLO 25088
#define XRAW0 32768
#define XRAW1 49152
#define WRAW0 65536
#define WRAW1 77824
#define PSMEM 90112

__global__ __launch_bounds__(128) void proj_mma_kernel(
    const float* __restrict__ x,
    const float* __restrict__ Wf,
    const float* __restrict__ Wg,
    const float* __restrict__ Wh)
{
    extern __shared__ __align__(16) char sm[];
    const uint32_t smb = smem_to_u32(sm);
    const int tid  = threadIdx.x;
    const int w    = tid >> 5;
    const int lane = tid & 31;
    const int b    = blockIdx.y;
    const int n0   = blockIdx.x * 128;

    const int a_r = lane & 15;
    const int a_c = (lane >> 4) << 3;
    const int tr  = (lane & 7) + 8 * ((lane >> 3) & 1);

    // prologue: cp.async chunk 0 into buf0
    {
#pragma unroll
        for (int i = 0; i < 8; i++) {
            int idx = tid + i * 128;
            int row = idx >> 5, seg = idx & 31;
            cpasync16(smb + XRAW0 + idx * 16,
                      x + ((size_t)(b * CIN + row)) * N3 + n0 + 4 * seg);
        }
#pragma unroll
        for (int i = 0; i < 6; i++) {
            int idx = tid + i * 128;
            int row = idx >> 3, seg = idx & 7;
            const float* Wsrc = (row < 32) ? Wf : ((row < 64) ? Wg : Wh);
            cpasync16(smb + WRAW0 + idx * 16, Wsrc + (row & 31) * CIN + 4 * seg);
        }
        CP_COMMIT();
    }

    float oacc[96];
#pragma unroll
    for (int i = 0; i < 96; i++) oacc[i] = 0.f;

    for (int cc = 0; cc < 8; cc++) {
        const int xraw = (cc & 1) ? XRAW1 : XRAW0;
        const int wraw = (cc & 1) ? WRAW1 : WRAW0;
        CP_WAIT0();
        __syncthreads();
        // convert raw fp32 -> split bf16 hi/lo
#pragma unroll
        for (int i = 0; i < 8; i++) {
            int idx = tid + i * 128;
            int row = idx >> 5, seg = idx & 31;
            float4 v = *(const float4*)(sm + xraw + idx * 16);
            uint32_t h0, l0, h1, l1;
            splitpair(v.x, v.y, h0, l0);
            splitpair(v.z, v.w, h1, l1);
            *(uint2*)(sm + PXHI + row * PXSTR + 8 * seg) = make_uint2(h0, h1);
            *(uint2*)(sm + PXLO + row * PXSTR + 8 * seg) = make_uint2(l0, l1);
        }
#pragma unroll
        for (int i = 0; i < 6; i++) {
            int idx = tid + i * 128;
            int row = idx >> 3, seg = idx & 7;
            float4 v = *(const float4*)(sm + wraw + idx * 16);
            uint32_t h0, l0, h1, l1;
            splitpair(v.x, v.y, h0, l0);
            splitpair(v.z, v.w, h1, l1);
            *(uint2*)(sm + PWHI + row * PWSTR + 8 * seg) = make_uint2(h0, h1);
            *(uint2*)(sm + PWLO + row * PWSTR + 8 * seg) = make_uint2(l0, l1);
        }
        __syncthreads();

        // issue cp.async for next chunk (overlaps compute)
        if (cc + 1 < 8) {
            const int cc0n = (cc + 1) * 32;
            const int xrawn = ((cc + 1) & 1) ? XRAW1 : XRAW0;
            const int wrawn = ((cc + 1) & 1) ? WRAW1 : WRAW0;
#pragma unroll
            for (int i = 0; i < 8; i++) {
                int idx = tid + i * 128;
                int row = idx >> 5, seg = idx & 31;
                cpasync16(smb + xrawn + idx * 16,
                          x + ((size_t)(b * CIN + cc0n + row)) * N3 + n0 + 4 * seg);
            }
#pragma unroll
            for (int i = 0; i < 6; i++) {
                int idx = tid + i * 128;
                int row = idx >> 3, seg = idx & 7;
                const float* Wsrc = (row < 32) ? Wf : ((row < 64) ? Wg : Wh);
                cpasync16(smb + wrawn + idx * 16, Wsrc + (row & 31) * CIN + cc0n + 4 * seg);
            }
            CP_COMMIT();
        }

#pragma unroll
        for (int ks = 0; ks < 2; ks++) {
            uint32_t bh[4][2], bl[4][2];
#pragma unroll
            for (int nt = 0; nt < 4; nt++) {
                uint32_t addr = smb + PXHI + (16 * ks + tr) * PXSTR + (32 * w + 8 * nt) * 2;
                ldsm2t(bh[nt], addr);
                ldsm2t(bl[nt], addr + (PXLO - PXHI));
            }
#pragma unroll
            for (int mt = 0; mt < 6; mt++) {
                uint32_t ah[4], al[4];
                uint32_t wadr = smb + PWHI + (16 * mt + a_r) * PWSTR + (16 * ks + a_c) * 2;
                ldsm4(ah, wadr);
                ldsm4(al, wadr + (PWLO - PWHI));
#pragma unroll
                for (int nt = 0; nt < 4; nt++) {
                    float* c = &oacc[(mt * 4 + nt) * 4];
                    mmabf(c, ah, bh[nt]);
                    mmabf(c, al, bh[nt]);
                    mmabf(c, ah, bl[nt]);
                }
            }
        }
    }

    // store: C[m=outch][n=pos]
    const int gid = lane >> 2;
    const int qid = lane & 3;
#pragma unroll
    for (int mt = 0; mt < 6; mt++) {
        float* dst = (mt < 2) ? g_f : ((mt < 4) ? g_graw : g_hraw);
        int ch = ((16 * mt) & 31) + gid;
#pragma unroll
        for (int nt = 0; nt < 4; nt++) {
            const float* c = &oacc[(mt * 4 + nt) * 4];
            int pos = n0 + 32 * w + 8 * nt + 2 * qid;
            size_t r0 = ((size_t)(b * CQ + ch)) * N3 + pos;
            size_t r1 = ((size_t)(b * CQ + ch + 8)) * N3 + pos;
            *(float2*)(dst + r0) = make_float2(c[0], c[1]);
            *(float2*)(dst + r1) = make_float2(c[2], c[3]);
        }
    }
}

// ---------------------------------------------------------------------------
// 2x2x2 max pool: [b][c][n] -> g_gp [b][m][c], g_hpT [b][c][m]
// ---------------------------------------------------------------------------
__global__ void pool_kernel()
{
    int idx = blockIdx.x * 256 + threadIdx.x;
    const int total = B_ * CQ * M3;
    if (idx >= total) return;
    int m = idx % M3;
    int c = (idx / M3) % CQ;
    int b = idx / (M3 * CQ);
    int md = m / 144, mh = (m / 12) % 12, mw = m % 12;

    const float* gbase = g_graw + ((size_t)(b * CQ + c)) * N3;
    const float* hbase = g_hraw + ((size_t)(b * CQ + c)) * N3;
    int n00 = (2 * md) * 576 + (2 * mh) * 24 + 2 * mw;

    float gmax = -INFINITY, hmax = -INFINITY;
#pragma unroll
    for (int dd = 0; dd < 2; dd++)
#pragma unroll
        for (int dh = 0; dh < 2; dh++) {
            int n = n00 + dd * 576 + dh * 24;
            float2 gv = *(const float2*)(gbase + n);
            float2 hv = *(const float2*)(hbase + n);
            gmax = fmaxf(gmax, fmaxf(gv.x, gv.y));
            hmax = fmaxf(hmax, fmaxf(hv.x, hv.y));
        }
    g_gp[((size_t)(b * M3 + m)) * CQ + c] = gmax;
    g_hpT[((size_t)(b * CQ + c)) * M3 + m] = hmax;
}

// ---------------------------------------------------------------------------
// Fused attention: register-resident P/O fragments, cp.async double-buffered
// G/H staging. Compute structure identical to the validated r14 kernel.
// ---------------------------------------------------------------------------
#define FSTR 40
#define GSTR 40
#define HSTR 72
#define WSTR 40
#define FHI 0
#define FLO 10240
#define GHI 20480
#define GLO 25600
#define HHI 30720
#define HLO 35328
#define WVH 0
#define WVL 20480
#define ARAWG0 40960
#define ARAWG1 49152
#define ARAWH0 57344
#define ARAWH1 65536
#define ASMEM 73728

__global__ __launch_bounds__(128) void attn_mma_kernel(
    const float* __restrict__ x,
    const float* __restrict__ Wv,
    const float* __restrict__ gamma_p,
    float* __restrict__ out)
{
    extern __shared__ __align__(16) char sm[];
    const uint32_t smb = smem_to_u32(sm);
    const int tid  = threadIdx.x;
    const int w    = tid >> 5;
    const int lane = tid & 31;
    const int b = blockIdx.y;
    const int qbase = blockIdx.x * QT;

    const float gma = *gamma_p;
    const float LOG2E = 1.4426950408889634f;

    const int a_r = lane & 15;
    const int a_c = (lane >> 4) << 3;
    const int b_r = lane & 7;
    const int b_c = ((lane >> 3) & 1) << 3;

    // prologue: cp.async G/H tile 0 into buf0
    {
#pragma unroll
        for (int i = 0; i < 4; i++) {
            int idx = tid + i * 128;
            int grow = idx >> 3, gseg = idx & 7;
            cpasync16(smb + ARAWG0 + idx * 16,
                      g_gp + ((size_t)(b * M3 + grow)) * CQ + 4 * gseg);
            int hrow = idx >> 4, hseg = idx & 15;
            cpasync16(smb + ARAWH0 + idx * 16,
                      g_hpT + ((size_t)(b * CQ + hrow)) * M3 + 4 * hseg);
        }
        CP_COMMIT();
    }

    // ---- load F tile from [b][c][n], fold log2e ----
    {
        const float* fb = g_f + (size_t)b * CQ * N3 + qbase + tid;
#pragma unroll
        for (int cp = 0; cp < 16; cp++) {
            float fa = fb[(size_t)(2 * cp) * N3] * LOG2E;
            float fc = fb[(size_t)(2 * cp + 1) * N3] * LOG2E;
            uint32_t h, l;
            splitpair(fa, fc, h, l);
            *(uint32_t*)(sm + FHI + (tid * FSTR + 2 * cp) * 2) = h;
            *(uint32_t*)(sm + FLO + (tid * FSTR + 2 * cp) * 2) = l;
        }
    }

    float oacc[2][4][4];
#pragma unroll
    for (int rt = 0; rt < 2; rt++)
#pragma unroll
        for (int n = 0; n < 4; n++)
#pragma unroll
            for (int i = 0; i < 4; i++) oacc[rt][n][i] = 0.f;
    float lpart[4] = {0.f, 0.f, 0.f, 0.f};

    for (int kt = 0; kt < NKT; kt++) {
        const int graw = (kt & 1) ? ARAWG1 : ARAWG0;
        const int hraw = (kt & 1) ? ARAWH1 : ARAWH0;
        CP_WAIT0();
        __syncthreads();
        // convert raw G (64 keys x 32 ch)
#pragma unroll
        for (int i = 0; i < 4; i++) {
            int idx = tid + i * 128;
            int row = idx >> 3, c = 4 * (idx & 7);
            float4 v = *(const float4*)(sm + graw + idx * 16);
            uint32_t h0, l0, h1, l1;
            splitpair(v.x, v.y, h0, l0);
            splitpair(v.z, v.w, h1, l1);
            *(uint2*)(sm + GHI + (row * GSTR + c) * 2) = make_uint2(h0, h1);
            *(uint2*)(sm + GLO + (row * GSTR + c) * 2) = make_uint2(l0, l1);
        }
        // convert raw H (32 ch x 64 keys)
#pragma unroll
        for (int i = 0; i < 4; i++) {
            int idx = tid + i * 128;
            int row = idx >> 4, j = 4 * (idx & 15);
            float4 v = *(const float4*)(sm + hraw + idx * 16);
            uint32_t h0, l0, h1, l1;
            splitpair(v.x, v.y, h0, l0);
            splitpair(v.z, v.w, h1, l1);
            *(uint2*)(sm + HHI + (row * HSTR + j) * 2) = make_uint2(h0, h1);
            *(uint2*)(sm + HLO + (row * HSTR + j) * 2) = make_uint2(l0, l1);
        }
        __syncthreads();

        // issue cp.async for next tile (overlaps compute)
        if (kt + 1 < NKT) {
            const int kb2 = (kt + 1) * KT;
            const int grawn = ((kt + 1) & 1) ? ARAWG1 : ARAWG0;
            const int hrawn = ((kt + 1) & 1) ? ARAWH1 : ARAWH0;
#pragma unroll
            for (int i = 0; i < 4; i++) {
                int idx = tid + i * 128;
                int grow = idx >> 3, gseg = idx & 7;
                cpasync16(smb + grawn + idx * 16,
                          g_gp + ((size_t)(b * M3 + kb2 + grow)) * CQ + 4 * gseg);
                int hrow = idx >> 4, hseg = idx & 15;
                cpasync16(smb + hrawn + idx * 16,
                          g_hpT + ((size_t)(b * CQ + hrow)) * M3 + kb2 + 4 * hseg);
            }
            CP_COMMIT();
        }

#pragma unroll
        for (int rt = 0; rt < 2; rt++) {
            // ---- S GEMM over 64 keys ----
            float sacc[8][4];
#pragma unroll
            for (int n = 0; n < 8; n++)
#pragma unroll
                for (int i = 0; i < 4; i++) sacc[n][i] = 0.f;

#pragma unroll
            for (int ks = 0; ks < 2; ks++) {
                uint32_t fh[4], fl[4];
                uint32_t fadr = smb + FHI + ((32 * w + 16 * rt + a_r) * FSTR + 16 * ks + a_c) * 2;
                ldsm4(fh, fadr);
                ldsm4(fl, fadr + FLO);
#pragma unroll
                for (int n = 0; n < 8; n++) {
                    uint32_t gh[2], gl[2];
                    uint32_t gadr = smb + GHI + ((8 * n + b_r) * GSTR + 16 * ks + b_c) * 2;
                    ldsm2(gh, gadr);
                    ldsm2(gl, gadr + (GLO - GHI));
                    mmabf(sacc[n], fh, gh);
                    mmabf(sacc[n], fl, gh);
                    mmabf(sacc[n], fh, gl);
                }
            }

            // ---- exp (base-2) + l partials ----
#pragma unroll
            for (int n = 0; n < 8; n++) {
#pragma unroll
                for (int i = 0; i < 4; i++) sacc[n][i] = ex2f(sacc[n][i]);
                lpart[rt * 2 + 0] += sacc[n][0] + sacc[n][1];
                lpart[rt * 2 + 1] += sacc[n][2] + sacc[n][3];
            }

            // ---- PV GEMM: P from registers ----
#pragma unroll
            for (int ks = 0; ks < 4; ks++) {
                uint32_t ph[4], pl[4];
                splitpair(sacc[2 * ks][0],     sacc[2 * ks][1],     ph[0], pl[0]);
                splitpair(sacc[2 * ks][2],     sacc[2 * ks][3],     ph[1], pl[1]);
                splitpair(sacc[2 * ks + 1][0], sacc[2 * ks + 1][1], ph[2], pl[2]);
                splitpair(sacc[2 * ks + 1][2], sacc[2 * ks + 1][3], ph[3], pl[3]);
#pragma unroll
                for (int n2 = 0; n2 < 4; n2++) {
                    uint32_t hh[2], hl[2];
                    uint32_t hadr = smb + HHI + ((8 * n2 + b_r) * HSTR + 16 * ks + b_c) * 2;
                    ldsm2(hh, hadr);
                    ldsm2(hl, hadr + (HLO - HHI));
                    mmabf(oacc[rt][n2], ph, hh);
                    mmabf(oacc[rt][n2], pl, hh);
                    mmabf(oacc[rt][n2], ph, hl);
                }
            }
        }
    }

    // ---- reduce l across quad lanes ----
    float inv[4];
#pragma unroll
    for (int i = 0; i < 4; i++) {
        float v = lpart[i];
        v += __shfl_xor_sync(0xFFFFFFFFu, v, 1);
        v += __shfl_xor_sync(0xFFFFFFFFu, v, 2);
        inv[i] = 1.0f / v;
    }

    // ---- build normalized O A-fragments in registers ----
    uint32_t ofh[2][2][4], ofl[2][2][4];
#pragma unroll
    for (int rt = 0; rt < 2; rt++) {
        float i0 = inv[rt * 2 + 0], i1 = inv[rt * 2 + 1];
#pragma unroll
        for (int ks = 0; ks < 2; ks++) {
            splitpair(oacc[rt][2 * ks][0] * i0,     oacc[rt][2 * ks][1] * i0,     ofh[rt][ks][0], ofl[rt][ks][0]);
            splitpair(oacc[rt][2 * ks][2] * i1,     oacc[rt][2 * ks][3] * i1,     ofh[rt][ks][1], ofl[rt][ks][1]);
            splitpair(oacc[rt][2 * ks + 1][0] * i0, oacc[rt][2 * ks + 1][1] * i0, ofh[rt][ks][2], ofl[rt][ks][2]);
            splitpair(oacc[rt][2 * ks + 1][2] * i1, oacc[rt][2 * ks + 1][3] * i1, ofh[rt][ks][3], ofl[rt][ks][3]);
        }
    }

    // ---- stage Wv (overlays F/G/H) ----
    __syncthreads();
#pragma unroll
    for (int h = 0; h < 2; h++) {
        int r = tid + 128 * h;
        const float4* src = (const float4*)(Wv + r * CQ);
#pragma unroll
        for (int i = 0; i < 8; i++) {
            float4 v = src[i];
            int c = i * 4;
            uint32_t h0, l0, h1, l1;
            splitpair(v.x, v.y, h0, l0);
            splitpair(v.z, v.w, h1, l1);
            *(uint2*)(sm + WVH + (r * WSTR + c) * 2) = make_uint2(h0, h1);
            *(uint2*)(sm + WVL + (r * WSTR + c) * 2) = make_uint2(l0, l1);
        }
    }
    __syncthreads();

    // ---- Out = O(128x32) . Wv(256x32)^T in 4 chunks of 64 couts ----
#pragma unroll 1
    for (int ch = 0; ch < 4; ch++) {
        float wacc[2][8][4];
#pragma unroll
        for (int rt = 0; rt < 2; rt++)
#pragma unroll
            for (int n = 0; n < 8; n++)
#pragma unroll
                for (int i = 0; i < 4; i++) wacc[rt][n][i] = 0.f;

#pragma unroll
        for (int ks = 0; ks < 2; ks++) {
#pragma unroll
            for (int n = 0; n < 8; n++) {
                uint32_t wh[2], wl[2];
                uint32_t wadr = smb + WVH + ((ch * 64 + 8 * n + b_r) * WSTR + 16 * ks + b_c) * 2;
                ldsm2(wh, wadr);
                ldsm2(wl, wadr + WVL);
#pragma unroll
                for (int rt = 0; rt < 2; rt++) {
                    mmabf(wacc[rt][n], ofh[rt][ks], wh);
                    mmabf(wacc[rt][n], ofl[rt][ks], wh);
                    mmabf(wacc[rt][n], ofh[rt][ks], wl);
                }
            }
        }

        // write out + residual (out layout [b][c][n])
#pragma unroll
        for (int rt = 0; rt < 2; rt++) {
            int q0 = qbase + 32 * w + 16 * rt + (lane >> 2);
#pragma unroll
            for (int n = 0; n < 8; n++) {
                int cc = ch * 64 + 8 * n + 2 * (lane & 3);
                size_t o0 = ((size_t)(b * CIN + cc)) * N3 + q0;
                out[o0]          = fmaf(gma, wacc[rt][n][0], x[o0]);
                out[o0 + N3]     = fmaf(gma, wacc[rt][n][1], x[o0 + N3]);
                out[o0 + 8]      = fmaf(gma, wacc[rt][n][2], x[o0 + 8]);
                out[o0 + N3 + 8] = fmaf(gma, wacc[rt][n][3], x[o0 + N3 + 8]);
            }
        }
    }
}

// ---------------------------------------------------------------------------
extern "C" void kernel_launch(void* const* d_in, const int* in_sizes, int n_in,
                              void* d_out, int out_size)
{
    const float* x     = (const float*)d_in[0];
    const float* Wf    = (const float*)d_in[1];
    const float* Wg    = (const float*)d_in[2];
    const float* Wh    = (const float*)d_in[3];
    const float* Wv    = (const float*)d_in[4];
    const float* gamma = (const float*)d_in[5];
    float* out = (float*)d_out;

    static bool attr_set = false;
    if (!attr_set) {
        cudaFuncSetAttribute(proj_mma_kernel,
                             cudaFuncAttributeMaxDynamicSharedMemorySize, PSMEM);
        cudaFuncSetAttribute(attn_mma_kernel,
                             cudaFuncAttributeMaxDynamicSharedMemorySize, ASMEM);
        attr_set = true;
    }

    dim3 pgrid(N3 / 128, B_);
    proj_mma_kernel<<<pgrid, 128, PSMEM>>>(x, Wf, Wg, Wh);

    int ptotal = B_ * CQ * M3;
    pool_kernel<<<(ptotal + 255) / 256, 256>>>();

    dim3 agrid(N3 / QT, B_);
    attn_mma_kernel<<<agrid, 128, ASMEM>>>(x, Wv, gamma, out);
}

// round 17
// speedup vs baseline: 1.2131x; 1.0117x over previous
#include <cuda_runtime.h>
#include <cuda_bf16.h>
#include <math.h>
#include <stdint.h>

#define B_   4
#define CIN  256
#define CQ   32
#define N3   13824   // 24^3
#define M3   1728    // 12^3
#define KT   64      // keys per tile
#define NKT  (M3/KT) // 27
#define QT   128     // queries per CTA

// ---- warp MMA helpers (baseline PTX, sm_75/80+ features) ----
__device__ __forceinline__ uint32_t smem_to_u32(const void* p) {
    uint32_t a;
    asm("{ .reg .u64 t; cvta.to.shared.u64 t, %1; cvt.u32.u64 %0, t; }" : "=r"(a) : "l"(p));
    return a;
}
__device__ __forceinline__ void ldsm4(uint32_t* r, uint32_t a) {
    asm volatile("ldmatrix.sync.aligned.m8n8.x4.shared.b16 {%0,%1,%2,%3}, [%4];"
        : "=r"(r[0]), "=r"(r[1]), "=r"(r[2]), "=r"(r[3]) : "r"(a));
}
__device__ __forceinline__ void ldsm2(uint32_t* r, uint32_t a) {
    asm volatile("ldmatrix.sync.aligned.m8n8.x2.shared.b16 {%0,%1}, [%2];"
        : "=r"(r[0]), "=r"(r[1]) : "r"(a));
}
__device__ __forceinline__ void ldsm2t(uint32_t* r, uint32_t a) {
    asm volatile("ldmatrix.sync.aligned.m8n8.x2.trans.shared.b16 {%0,%1}, [%2];"
        : "=r"(r[0]), "=r"(r[1]) : "r"(a));
}
__device__ __forceinline__ void mmabf(float* c, const uint32_t* a, const uint32_t* b) {
    asm volatile("mma.sync.aligned.m16n8k16.row.col.f32.bf16.bf16.f32 "
        "{%0,%1,%2,%3}, {%4,%5,%6,%7}, {%8,%9}, {%0,%1,%2,%3};"
        : "+f"(c[0]), "+f"(c[1]), "+f"(c[2]), "+f"(c[3])
        : "r"(a[0]), "r"(a[1]), "r"(a[2]), "r"(a[3]), "r"(b[0]), "r"(b[1]));
}
__device__ __forceinline__ float ex2f(float x) {
    float r; asm("ex2.approx.ftz.f32 %0, %1;" : "=f"(r) : "f"(x)); return r;
}
__device__ __forceinline__ void cpasync16(uint32_t dst, const void* src) {
    asm volatile("cp.async.ca.shared.global [%0], [%1], 16;" :: "r"(dst), "l"(src));
}
#define CP_COMMIT() asm volatile("cp.async.commit_group;" ::: "memory")
#define CP_WAIT0()  asm volatile("cp.async.wait_group 0;" ::: "memory")

// split (a,b) -> bf16x2 hi reg + bf16x2 lo reg
__device__ __forceinline__ void splitpair(float a, float b, uint32_t& hi, uint32_t& lo) {
    __nv_bfloat162 h = __floats2bfloat162_rn(a, b);
    float ra = a - __bfloat162float(h.x);
    float rb = b - __bfloat162float(h.y);
    __nv_bfloat162 l = __floats2bfloat162_rn(ra, rb);
    hi = *(uint32_t*)&h;
    lo = *(uint32_t*)&l;
}

// Scratch (device globals). Layouts:
//   g_f, g_graw, g_hraw : [b][c][n]  (channel-major)
//   g_gp                : [b][m][c]
//   g_hpT               : [b][c][m]
__device__ float g_f[B_ * CQ * N3];
__device__ float g_graw[B_ * CQ * N3];
__device__ float g_hraw[B_ * CQ * N3];
__device__ float g_gp[B_ * M3 * CQ];
__device__ float g_hpT[B_ * CQ * M3];

// ---------------------------------------------------------------------------
// Projection via mma.sync + cp.async double-buffered staging.
// out[96, n] = W[96,256] x x[256, n] (3-term split). Output [b][c][n].
// ---------------------------------------------------------------------------
#define PXSTR 272   // bytes per x row (128 bf16 + 8 pad)
#define PWSTR 80    // bytes per W row (32 bf16 + 8 pad)
#define PXHI 0
#define PXLO 8704
#define PWHI 17408
#define PWLO 25088
#define XRAW0 32768
#define XRAW1 49152
#define WRAW0 65536
#define WRAW1 77824
#define PSMEM 90112

__global__ __launch_bounds__(128) void proj_mma_kernel(
    const float* __restrict__ x,
    const float* __restrict__ Wf,
    const float* __restrict__ Wg,
    const float* __restrict__ Wh)
{
    extern __shared__ __align__(16) char sm[];
    const uint32_t smb = smem_to_u32(sm);
    const int tid  = threadIdx.x;
    const int w    = tid >> 5;
    const int lane = tid & 31;
    const int b    = blockIdx.y;
    const int n0   = blockIdx.x * 128;

    const int a_r = lane & 15;
    const int a_c = (lane >> 4) << 3;
    const int tr  = (lane & 7) + 8 * ((lane >> 3) & 1);

    // prologue: cp.async chunk 0 into buf0
    {
#pragma unroll
        for (int i = 0; i < 8; i++) {
            int idx = tid + i * 128;
            int row = idx >> 5, seg = idx & 31;
            cpasync16(smb + XRAW0 + idx * 16,
                      x + ((size_t)(b * CIN + row)) * N3 + n0 + 4 * seg);
        }
#pragma unroll
        for (int i = 0; i < 6; i++) {
            int idx = tid + i * 128;
            int row = idx >> 3, seg = idx & 7;
            const float* Wsrc = (row < 32) ? Wf : ((row < 64) ? Wg : Wh);
            cpasync16(smb + WRAW0 + idx * 16, Wsrc + (row & 31) * CIN + 4 * seg);
        }
        CP_COMMIT();
    }

    float oacc[96];
#pragma unroll
    for (int i = 0; i < 96; i++) oacc[i] = 0.f;

    for (int cc = 0; cc < 8; cc++) {
        const int xraw = (cc & 1) ? XRAW1 : XRAW0;
        const int wraw = (cc & 1) ? WRAW1 : WRAW0;
        CP_WAIT0();
        __syncthreads();
        // convert raw fp32 -> split bf16 hi/lo
#pragma unroll
        for (int i = 0; i < 8; i++) {
            int idx = tid + i * 128;
            int row = idx >> 5, seg = idx & 31;
            float4 v = *(const float4*)(sm + xraw + idx * 16);
            uint32_t h0, l0, h1, l1;
            splitpair(v.x, v.y, h0, l0);
            splitpair(v.z, v.w, h1, l1);
            *(uint2*)(sm + PXHI + row * PXSTR + 8 * seg) = make_uint2(h0, h1);
            *(uint2*)(sm + PXLO + row * PXSTR + 8 * seg) = make_uint2(l0, l1);
        }
#pragma unroll
        for (int i = 0; i < 6; i++) {
            int idx = tid + i * 128;
            int row = idx >> 3, seg = idx & 7;
            float4 v = *(const float4*)(sm + wraw + idx * 16);
            uint32_t h0, l0, h1, l1;
            splitpair(v.x, v.y, h0, l0);
            splitpair(v.z, v.w, h1, l1);
            *(uint2*)(sm + PWHI + row * PWSTR + 8 * seg) = make_uint2(h0, h1);
            *(uint2*)(sm + PWLO + row * PWSTR + 8 * seg) = make_uint2(l0, l1);
        }
        __syncthreads();

        // issue cp.async for next chunk (overlaps compute)
        if (cc + 1 < 8) {
            const int cc0n = (cc + 1) * 32;
            const int xrawn = ((cc + 1) & 1) ? XRAW1 : XRAW0;
            const int wrawn = ((cc + 1) & 1) ? WRAW1 : WRAW0;
#pragma unroll
            for (int i = 0; i < 8; i++) {
                int idx = tid + i * 128;
                int row = idx >> 5, seg = idx & 31;
                cpasync16(smb + xrawn + idx * 16,
                          x + ((size_t)(b * CIN + cc0n + row)) * N3 + n0 + 4 * seg);
            }
#pragma unroll
            for (int i = 0; i < 6; i++) {
                int idx = tid + i * 128;
                int row = idx >> 3, seg = idx & 7;
                const float* Wsrc = (row < 32) ? Wf : ((row < 64) ? Wg : Wh);
                cpasync16(smb + wrawn + idx * 16, Wsrc + (row & 31) * CIN + cc0n + 4 * seg);
            }
            CP_COMMIT();
        }

#pragma unroll
        for (int ks = 0; ks < 2; ks++) {
            uint32_t bh[4][2], bl[4][2];
#pragma unroll
            for (int nt = 0; nt < 4; nt++) {
                uint32_t addr = smb + PXHI + (16 * ks + tr) * PXSTR + (32 * w + 8 * nt) * 2;
                ldsm2t(bh[nt], addr);
                ldsm2t(bl[nt], addr + (PXLO - PXHI));
            }
#pragma unroll
            for (int mt = 0; mt < 6; mt++) {
                uint32_t ah[4], al[4];
                uint32_t wadr = smb + PWHI + (16 * mt + a_r) * PWSTR + (16 * ks + a_c) * 2;
                ldsm4(ah, wadr);
                ldsm4(al, wadr + (PWLO - PWHI));
                // term-major ordering: dependent MMAs separated by 3 others
#pragma unroll
                for (int nt = 0; nt < 4; nt++)
                    mmabf(&oacc[(mt * 4 + nt) * 4], ah, bh[nt]);
#pragma unroll
                for (int nt = 0; nt < 4; nt++)
                    mmabf(&oacc[(mt * 4 + nt) * 4], al, bh[nt]);
#pragma unroll
                for (int nt = 0; nt < 4; nt++)
                    mmabf(&oacc[(mt * 4 + nt) * 4], ah, bl[nt]);
            }
        }
    }

    // store: C[m=outch][n=pos]
    const int gid = lane >> 2;
    const int qid = lane & 3;
#pragma unroll
    for (int mt = 0; mt < 6; mt++) {
        float* dst = (mt < 2) ? g_f : ((mt < 4) ? g_graw : g_hraw);
        int ch = ((16 * mt) & 31) + gid;
#pragma unroll
        for (int nt = 0; nt < 4; nt++) {
            const float* c = &oacc[(mt * 4 + nt) * 4];
            int pos = n0 + 32 * w + 8 * nt + 2 * qid;
            size_t r0 = ((size_t)(b * CQ + ch)) * N3 + pos;
            size_t r1 = ((size_t)(b * CQ + ch + 8)) * N3 + pos;
            *(float2*)(dst + r0) = make_float2(c[0], c[1]);
            *(float2*)(dst + r1) = make_float2(c[2], c[3]);
        }
    }
}

// ---------------------------------------------------------------------------
// 2x2x2 max pool: [b][c][n] -> g_gp [b][m][c], g_hpT [b][c][m]
// ---------------------------------------------------------------------------
__global__ void pool_kernel()
{
    int idx = blockIdx.x * 256 + threadIdx.x;
    const int total = B_ * CQ * M3;
    if (idx >= total) return;
    int m = idx % M3;
    int c = (idx / M3) % CQ;
    int b = idx / (M3 * CQ);
    int md = m / 144, mh = (m / 12) % 12, mw = m % 12;

    const float* gbase = g_graw + ((size_t)(b * CQ + c)) * N3;
    const float* hbase = g_hraw + ((size_t)(b * CQ + c)) * N3;
    int n00 = (2 * md) * 576 + (2 * mh) * 24 + 2 * mw;

    float gmax = -INFINITY, hmax = -INFINITY;
#pragma unroll
    for (int dd = 0; dd < 2; dd++)
#pragma unroll
        for (int dh = 0; dh < 2; dh++) {
            int n = n00 + dd * 576 + dh * 24;
            float2 gv = *(const float2*)(gbase + n);
            float2 hv = *(const float2*)(hbase + n);
            gmax = fmaxf(gmax, fmaxf(gv.x, gv.y));
            hmax = fmaxf(hmax, fmaxf(hv.x, hv.y));
        }
    g_gp[((size_t)(b * M3 + m)) * CQ + c] = gmax;
    g_hpT[((size_t)(b * CQ + c)) * M3 + m] = hmax;
}

// ---------------------------------------------------------------------------
// Fused attention: register-resident P/O fragments, cp.async double-buffered
// G/H staging, term-major MMA ordering with preloaded B-fragments.
// ---------------------------------------------------------------------------
#define FSTR 40
#define GSTR 40
#define HSTR 72
#define WSTR 40
#define FHI 0
#define FLO 10240
#define GHI 20480
#define GLO 25600
#define HHI 30720
#define HLO 35328
#define WVH 0
#define WVL 20480
#define ARAWG0 40960
#define ARAWG1 49152
#define ARAWH0 57344
#define ARAWH1 65536
#define ASMEM 73728

__global__ __launch_bounds__(128) void attn_mma_kernel(
    const float* __restrict__ x,
    const float* __restrict__ Wv,
    const float* __restrict__ gamma_p,
    float* __restrict__ out)
{
    extern __shared__ __align__(16) char sm[];
    const uint32_t smb = smem_to_u32(sm);
    const int tid  = threadIdx.x;
    const int w    = tid >> 5;
    const int lane = tid & 31;
    const int b = blockIdx.y;
    const int qbase = blockIdx.x * QT;

    const float gma = *gamma_p;
    const float LOG2E = 1.4426950408889634f;

    const int a_r = lane & 15;
    const int a_c = (lane >> 4) << 3;
    const int b_r = lane & 7;
    const int b_c = ((lane >> 3) & 1) << 3;

    // prologue: cp.async G/H tile 0 into buf0
    {
#pragma unroll
        for (int i = 0; i < 4; i++) {
            int idx = tid + i * 128;
            int grow = idx >> 3, gseg = idx & 7;
            cpasync16(smb + ARAWG0 + idx * 16,
                      g_gp + ((size_t)(b * M3 + grow)) * CQ + 4 * gseg);
            int hrow = idx >> 4, hseg = idx & 15;
            cpasync16(smb + ARAWH0 + idx * 16,
                      g_hpT + ((size_t)(b * CQ + hrow)) * M3 + 4 * hseg);
        }
        CP_COMMIT();
    }

    // ---- load F tile from [b][c][n], fold log2e ----
    {
        const float* fb = g_f + (size_t)b * CQ * N3 + qbase + tid;
#pragma unroll
        for (int cp = 0; cp < 16; cp++) {
            float fa = fb[(size_t)(2 * cp) * N3] * LOG2E;
            float fc = fb[(size_t)(2 * cp + 1) * N3] * LOG2E;
            uint32_t h, l;
            splitpair(fa, fc, h, l);
            *(uint32_t*)(sm + FHI + (tid * FSTR + 2 * cp) * 2) = h;
            *(uint32_t*)(sm + FLO + (tid * FSTR + 2 * cp) * 2) = l;
        }
    }

    float oacc[2][4][4];
#pragma unroll
    for (int rt = 0; rt < 2; rt++)
#pragma unroll
        for (int n = 0; n < 4; n++)
#pragma unroll
            for (int i = 0; i < 4; i++) oacc[rt][n][i] = 0.f;
    float lpart[4] = {0.f, 0.f, 0.f, 0.f};

    for (int kt = 0; kt < NKT; kt++) {
        const int graw = (kt & 1) ? ARAWG1 : ARAWG0;
        const int hraw = (kt & 1) ? ARAWH1 : ARAWH0;
        CP_WAIT0();
        __syncthreads();
        // convert raw G (64 keys x 32 ch)
#pragma unroll
        for (int i = 0; i < 4; i++) {
            int idx = tid + i * 128;
            int row = idx >> 3, c = 4 * (idx & 7);
            float4 v = *(const float4*)(sm + graw + idx * 16);
            uint32_t h0, l0, h1, l1;
            splitpair(v.x, v.y, h0, l0);
            splitpair(v.z, v.w, h1, l1);
            *(uint2*)(sm + GHI + (row * GSTR + c) * 2) = make_uint2(h0, h1);
            *(uint2*)(sm + GLO + (row * GSTR + c) * 2) = make_uint2(l0, l1);
        }
        // convert raw H (32 ch x 64 keys)
#pragma unroll
        for (int i = 0; i < 4; i++) {
            int idx = tid + i * 128;
            int row = idx >> 4, j = 4 * (idx & 15);
            float4 v = *(const float4*)(sm + hraw + idx * 16);
            uint32_t h0, l0, h1, l1;
            splitpair(v.x, v.y, h0, l0);
            splitpair(v.z, v.w, h1, l1);
            *(uint2*)(sm + HHI + (row * HSTR + j) * 2) = make_uint2(h0, h1);
            *(uint2*)(sm + HLO + (row * HSTR + j) * 2) = make_uint2(l0, l1);
        }
        __syncthreads();

        // issue cp.async for next tile (overlaps compute)
        if (kt + 1 < NKT) {
            const int kb2 = (kt + 1) * KT;
            const int grawn = ((kt + 1) & 1) ? ARAWG1 : ARAWG0;
            const int hrawn = ((kt + 1) & 1) ? ARAWH1 : ARAWH0;
#pragma unroll
            for (int i = 0; i < 4; i++) {
                int idx = tid + i * 128;
                int grow = idx >> 3, gseg = idx & 7;
                cpasync16(smb + grawn + idx * 16,
                          g_gp + ((size_t)(b * M3 + kb2 + grow)) * CQ + 4 * gseg);
                int hrow = idx >> 4, hseg = idx & 15;
                cpasync16(smb + hrawn + idx * 16,
                          g_hpT + ((size_t)(b * CQ + hrow)) * M3 + kb2 + 4 * hseg);
            }
            CP_COMMIT();
        }

#pragma unroll
        for (int rt = 0; rt < 2; rt++) {
            // ---- S GEMM over 64 keys: preload all B-frags, term-major ----
            float sacc[8][4];
#pragma unroll
            for (int n = 0; n < 8; n++)
#pragma unroll
                for (int i = 0; i < 4; i++) sacc[n][i] = 0.f;

#pragma unroll
            for (int ks = 0; ks < 2; ks++) {
                uint32_t fh[4], fl[4];
                uint32_t fadr = smb + FHI + ((32 * w + 16 * rt + a_r) * FSTR + 16 * ks + a_c) * 2;
                ldsm4(fh, fadr);
                ldsm4(fl, fadr + FLO);
                uint32_t gh[8][2], gl[8][2];
#pragma unroll
                for (int n = 0; n < 8; n++) {
                    uint32_t gadr = smb + GHI + ((8 * n + b_r) * GSTR + 16 * ks + b_c) * 2;
                    ldsm2(gh[n], gadr);
                    ldsm2(gl[n], gadr + (GLO - GHI));
                }
#pragma unroll
                for (int n = 0; n < 8; n++) mmabf(sacc[n], fh, gh[n]);
#pragma unroll
                for (int n = 0; n < 8; n++) mmabf(sacc[n], fl, gh[n]);
#pragma unroll
                for (int n = 0; n < 8; n++) mmabf(sacc[n], fh, gl[n]);
            }

            // ---- exp (base-2) + l partials ----
#pragma unroll
            for (int n = 0; n < 8; n++) {
#pragma unroll
                for (int i = 0; i < 4; i++) sacc[n][i] = ex2f(sacc[n][i]);
                lpart[rt * 2 + 0] += sacc[n][0] + sacc[n][1];
                lpart[rt * 2 + 1] += sacc[n][2] + sacc[n][3];
            }

            // ---- PV GEMM: P from registers; preload H frags, term-major ----
#pragma unroll
            for (int ks = 0; ks < 4; ks++) {
                uint32_t ph[4], pl[4];
                splitpair(sacc[2 * ks][0],     sacc[2 * ks][1],     ph[0], pl[0]);
                splitpair(sacc[2 * ks][2],     sacc[2 * ks][3],     ph[1], pl[1]);
                splitpair(sacc[2 * ks + 1][0], sacc[2 * ks + 1][1], ph[2], pl[2]);
                splitpair(sacc[2 * ks + 1][2], sacc[2 * ks + 1][3], ph[3], pl[3]);
                uint32_t hh[4][2], hl[4][2];
#pragma unroll
                for (int n2 = 0; n2 < 4; n2++) {
                    uint32_t hadr = smb + HHI + ((8 * n2 + b_r) * HSTR + 16 * ks + b_c) * 2;
                    ldsm2(hh[n2], hadr);
                    ldsm2(hl[n2], hadr + (HLO - HHI));
                }
#pragma unroll
                for (int n2 = 0; n2 < 4; n2++) mmabf(oacc[rt][n2], ph, hh[n2]);
#pragma unroll
                for (int n2 = 0; n2 < 4; n2++) mmabf(oacc[rt][n2], pl, hh[n2]);
#pragma unroll
                for (int n2 = 0; n2 < 4; n2++) mmabf(oacc[rt][n2], ph, hl[n2]);
            }
        }
    }

    // ---- reduce l across quad lanes ----
    float inv[4];
#pragma unroll
    for (int i = 0; i < 4; i++) {
        float v = lpart[i];
        v += __shfl_xor_sync(0xFFFFFFFFu, v, 1);
        v += __shfl_xor_sync(0xFFFFFFFFu, v, 2);
        inv[i] = 1.0f / v;
    }

    // ---- build normalized O A-fragments in registers ----
    uint32_t ofh[2][2][4], ofl[2][2][4];
#pragma unroll
    for (int rt = 0; rt < 2; rt++) {
        float i0 = inv[rt * 2 + 0], i1 = inv[rt * 2 + 1];
#pragma unroll
        for (int ks = 0; ks < 2; ks++) {
            splitpair(oacc[rt][2 * ks][0] * i0,     oacc[rt][2 * ks][1] * i0,     ofh[rt][ks][0], ofl[rt][ks][0]);
            splitpair(oacc[rt][2 * ks][2] * i1,     oacc[rt][2 * ks][3] * i1,     ofh[rt][ks][1], ofl[rt][ks][1]);
            splitpair(oacc[rt][2 * ks + 1][0] * i0, oacc[rt][2 * ks + 1][1] * i0, ofh[rt][ks][2], ofl[rt][ks][2]);
            splitpair(oacc[rt][2 * ks + 1][2] * i1, oacc[rt][2 * ks + 1][3] * i1, ofh[rt][ks][3], ofl[rt][ks][3]);
        }
    }

    // ---- stage Wv (overlays F/G/H) ----
    __syncthreads();
#pragma unroll
    for (int h = 0; h < 2; h++) {
        int r = tid + 128 * h;
        const float4* src = (const float4*)(Wv + r * CQ);
#pragma unroll
        for (int i = 0; i < 8; i++) {
            float4 v = src[i];
            int c = i * 4;
            uint32_t h0, l0, h1, l1;
            splitpair(v.x, v.y, h0, l0);
            splitpair(v.z, v.w, h1, l1);
            *(uint2*)(sm + WVH + (r * WSTR + c) * 2) = make_uint2(h0, h1);
            *(uint2*)(sm + WVL + (r * WSTR + c) * 2) = make_uint2(l0, l1);
        }
    }
    __syncthreads();

    // ---- Out = O(128x32) . Wv(256x32)^T in 4 chunks of 64 couts ----
#pragma unroll 1
    for (int ch = 0; ch < 4; ch++) {
        float wacc[2][8][4];
#pragma unroll
        for (int rt = 0; rt < 2; rt++)
#pragma unroll
            for (int n = 0; n < 8; n++)
#pragma unroll
                for (int i = 0; i < 4; i++) wacc[rt][n][i] = 0.f;

#pragma unroll
        for (int ks = 0; ks < 2; ks++) {
#pragma unroll
            for (int n = 0; n < 8; n++) {
                uint32_t wh[2], wl[2];
                uint32_t wadr = smb + WVH + ((ch * 64 + 8 * n + b_r) * WSTR + 16 * ks + b_c) * 2;
                ldsm2(wh, wadr);
                ldsm2(wl, wadr + WVL);
#pragma unroll
                for (int rt = 0; rt < 2; rt++) mmabf(wacc[rt][n], ofh[rt][ks], wh);
#pragma unroll
                for (int rt = 0; rt < 2; rt++) mmabf(wacc[rt][n], ofl[rt][ks], wh);
#pragma unroll
                for (int rt = 0; rt < 2; rt++) mmabf(wacc[rt][n], ofh[rt][ks], wl);
            }
        }

        // write out + residual (out layout [b][c][n])
#pragma unroll
        for (int rt = 0; rt < 2; rt++) {
            int q0 = qbase + 32 * w + 16 * rt + (lane >> 2);
#pragma unroll
            for (int n = 0; n < 8; n++) {
                int cc = ch * 64 + 8 * n + 2 * (lane & 3);
                size_t o0 = ((size_t)(b * CIN + cc)) * N3 + q0;
                out[o0]          = fmaf(gma, wacc[rt][n][0], x[o0]);
                out[o0 + N3]     = fmaf(gma, wacc[rt][n][1], x[o0 + N3]);
                out[o0 + 8]      = fmaf(gma, wacc[rt][n][2], x[o0 + 8]);
                out[o0 + N3 + 8] = fmaf(gma, wacc[rt][n][3], x[o0 + N3 + 8]);
            }
        }
    }
}

// ---------------------------------------------------------------------------
extern "C" void kernel_launch(void* const* d_in, const int* in_sizes, int n_in,
                              void* d_out, int out_size)
{
    const float* x     = (const float*)d_in[0];
    const float* Wf    = (const float*)d_in[1];
    const float* Wg    = (const float*)d_in[2];
    const float* Wh    = (const float*)d_in[3];
    const float* Wv    = (const float*)d_in[4];
    const float* gamma = (const float*)d_in[5];
    float* out = (float*)d_out;

    static bool attr_set = false;
    if (!attr_set) {
        cudaFuncSetAttribute(proj_mma_kernel,
                             cudaFuncAttributeMaxDynamicSharedMemorySize, PSMEM);
        cudaFuncSetAttribute(attn_mma_kernel,
                             cudaFuncAttributeMaxDynamicSharedMemorySize, ASMEM);
        attr_set = true;
    }

    dim3 pgrid(N3 / 128, B_);
    proj_mma_kernel<<<pgrid, 128, PSMEM>>>(x, Wf, Wg, Wh);

    int ptotal = B_ * CQ * M3;
    pool_kernel<<<(ptotal + 255) / 256, 256>>>();

    dim3 agrid(N3 / QT, B_);
    attn_mma_kernel<<<agrid, 128, ASMEM>>>(x, Wv, gamma, out);
}